// round 13
// baseline (speedup 1.0000x reference)
#include <cuda_runtime.h>
#include <math.h>

#define ISZ 256
#define NV  512
#define NF  1024
#define CH  256          // faces per chunk (4 chunks per tile)

__device__ unsigned g_cov[256 * 4 * 8];   // [tile][chunk][warp-word], plain STG
__device__ float    g_tile_loss[256];
__device__ unsigned g_tctr[256];          // per-tile arrival counters (wrap at 3)
__device__ unsigned g_ctr = 0;            // tile-done counter (wrap at 255)

struct Cam {
    float ex, ey, ez;
    float r00, r01, r02, r10, r11, r12, r20, r21, r22;
    float width;
};

// ---------------------------------------------------------------------------
// Grid 1024 = 256 tiles (16x16 px) x 4 face-chunks, 256 threads.
// Prep: bbox + conservative SAT edge cull, 1 face/thread, ballot-compact.
// Fast path: if any face's three planes are all > 1e-3 over the whole tile
// rect, every pixel center is inside it -> skip the per-pixel scan.
// Coverage merged via plain per-(tile,chunk) STG words (overwritten every
// replay -> deterministic), ordered by fence + wrap counters.
// Depth test dropped (provably always passes for interior pixels here).
// ---------------------------------------------------------------------------
__global__ __launch_bounds__(256) void fused_kernel(
    const float* __restrict__ verts,
    const int*   __restrict__ faces,
    const float* __restrict__ ref,
    float* __restrict__ out,
    Cam cam)
{
    __shared__ float  sx[NV], sy[NV];
    __shared__ float4 s_f0[CH];      // A0, B0, C0, A1
    __shared__ float2 s_f1[CH];      // B1, C1
    __shared__ float  s_red[8];
    __shared__ int    s_cnt, s_full, s_tlast, s_glast;

    const unsigned FULL = 0xffffffffu;
    int t     = threadIdx.x;
    int lane  = t & 31;
    int warp  = t >> 5;
    int tile  = blockIdx.x >> 2;     // 0..255
    int chunk = blockIdx.x & 3;      // 0..3
    int tx    = tile & 15;
    int ty    = tile >> 4;
    if (t == 0) { s_cnt = 0; s_full = 0; s_tlast = 0; s_glast = 0; }

    // pixel coords for this thread
    int c = 16*tx + (t & 15);
    int r = 16*ty + (t >> 4);

    // ---- Prefetch face indices + ref value (overlap the transform chain) ----
    int f  = chunk * CH + t;
    int i0 = faces[3*f+0], i1 = faces[3*f+1], i2 = faces[3*f+2];
    float refv = ref[r * ISZ + c];

    // ---- Vertex transform: 2 verts/thread, single MUFU.RCP each ----
    #pragma unroll
    for (int v = t; v < NV; v += 256) {
        float vx = verts[3*v+0] - cam.ex;
        float vy = verts[3*v+1] - cam.ey;
        float vz = verts[3*v+2] - cam.ez;
        float cx = vx*cam.r00 + vy*cam.r01 + vz*cam.r02;
        float cy = vx*cam.r10 + vy*cam.r11 + vz*cam.r12;
        float cz = vx*cam.r20 + vy*cam.r21 + vz*cam.r22;
        float rzw = __fdividef(1.0f, cz * cam.width);
        sx[v] = cx * rzw;
        sy[v] = cy * rzw;
    }
    __syncthreads();

    // tile pixel-center bounds in NDC
    float txmin = (2.0f * (16*tx)            + 1.0f - 256.0f) * (1.0f/256.0f);
    float txmax = (2.0f * (16*tx + 15)       + 1.0f - 256.0f) * (1.0f/256.0f);
    float tymax = (2.0f * (255 - 16*ty)      + 1.0f - 256.0f) * (1.0f/256.0f);
    float tymin = (2.0f * (255 - (16*ty+15)) + 1.0f - 256.0f) * (1.0f/256.0f);

    // ---- Prep: 1 face/thread, bbox + SAT cull + full-cover detect ----
    {
        float x0 = sx[i0], x1 = sx[i1], x2 = sx[i2];
        float y0 = sy[i0], y1 = sy[i1], y2 = sy[i2];

        float denom = (y1 - y2) * (x0 - x2) + (x2 - x1) * (y0 - y2);
        bool  valid = fabsf(denom) > 1e-9f;

        float bxmin = fminf(x0, fminf(x1, x2));
        float bxmax = fmaxf(x0, fmaxf(x1, x2));
        float bymin = fminf(y0, fminf(y1, y2));
        float bymax = fmaxf(y0, fmaxf(y1, y2));

        bool acc = valid && (bxmin <= txmax) && (bxmax >= txmin) &&
                            (bymin <= tymax) && (bymax >= tymin);

        float rd = __fdividef(1.0f, denom);  // garbage if invalid; acc=false then
        float A0 = (y1 - y2) * rd, B0 = (x2 - x1) * rd;
        float A1 = (y2 - y0) * rd, B1 = (x0 - x2) * rd;
        float C0 = -(A0 * x2 + B0 * y2);
        float C1 = -(A1 * x2 + B1 * y2);
        float A2 = -(A0 + A1), B2 = -(B0 + B1), C2 = 1.0f - C0 - C1;

        // conservative max of each plane over the tile's pixel-center rect
        float e0 = A0 * (A0 > 0.0f ? txmax : txmin)
                 + B0 * (B0 > 0.0f ? tymax : tymin) + C0;
        float e1 = A1 * (A1 > 0.0f ? txmax : txmin)
                 + B1 * (B1 > 0.0f ? tymax : tymin) + C1;
        float e2 = A2 * (A2 > 0.0f ? txmax : txmin)
                 + B2 * (B2 > 0.0f ? tymax : tymin) + C2;
        acc = acc && (e0 > -1e-3f) && (e1 > -1e-3f) && (e2 > -1e-3f);

        // conservative min of each plane over the rect: full-cover test
        float m0 = A0 * (A0 > 0.0f ? txmin : txmax)
                 + B0 * (B0 > 0.0f ? tymin : tymax) + C0;
        float m1 = A1 * (A1 > 0.0f ? txmin : txmax)
                 + B1 * (B1 > 0.0f ? tymin : tymax) + C1;
        float m2 = A2 * (A2 > 0.0f ? txmin : txmax)
                 + B2 * (B2 > 0.0f ? tymin : tymax) + C2;
        if (valid && fminf(fminf(m0, m1), m2) > 1e-3f)
            s_full = 1;                      // benign race, same value

        unsigned bal = __ballot_sync(FULL, acc);
        int base = 0;
        if (lane == 0 && bal) base = atomicAdd(&s_cnt, __popc(bal));
        base = __shfl_sync(FULL, base, 0);
        if (acc) {
            int pos = base + __popc(bal & ((1u << lane) - 1u));
            s_f0[pos] = make_float4(A0, B0, C0, A1);
            s_f1[pos] = make_float2(B1, C1);
        }
    }
    __syncthreads();
    int n = s_cnt;

    bool cov;
    if (s_full) {
        cov = true;                          // some face covers the whole tile
    } else {
        // ---- Per-pixel running-max plane scan ----
        float xs = (2.0f * c + 1.0f - 256.0f) * (1.0f/256.0f);
        float ys = (2.0f * (255 - r) + 1.0f - 256.0f) * (1.0f/256.0f);

        float best = -1e30f;
        #pragma unroll 8
        for (int j = 0; j < n; j++) {
            float4 f0 = s_f0[j];
            float2 f1 = s_f1[j];
            float w0 = f0.x * xs + f0.y * ys + f0.z;
            float w1 = f0.w * xs + f1.x * ys + f1.y;
            float w2 = 1.0f - w0 - w1;
            best = fmaxf(best, fminf(fminf(w0, w1), w2));
            if ((j & 15) == 15 && __all_sync(FULL, best > 0.0f)) break;
        }
        cov = best > 0.0f;
    }

    // ---- Write coverage word (unconditional STG -> replay-deterministic) ----
    unsigned bits = __ballot_sync(FULL, cov);
    if (lane == 0)
        g_cov[(tile * 4 + chunk) * 8 + warp] = bits;
    __syncthreads();

    // ---- Per-tile arrival; 4th block computes the tile's loss ----
    if (t == 0) {
        __threadfence();
        unsigned rank = atomicInc(&g_tctr[tile], 3u);   // wraps -> replay safe
        s_tlast = (rank == 3u);
    }
    __syncthreads();

    if (s_tlast) {
        volatile unsigned* vc = g_cov + tile * 32;
        unsigned w = vc[warp] | vc[8 + warp] | vc[16 + warp] | vc[24 + warp];
        float covf = (float)((w >> lane) & 1u);
        float d = covf - refv;
        float v = d * d;
        #pragma unroll
        for (int off = 16; off > 0; off >>= 1)
            v += __shfl_xor_sync(FULL, v, off);
        if (lane == 0) s_red[warp] = v;
        __syncthreads();
        if (t == 0) {
            float acc = s_red[0] + s_red[1] + s_red[2] + s_red[3]
                      + s_red[4] + s_red[5] + s_red[6] + s_red[7];
            g_tile_loss[tile] = acc;
            __threadfence();
            unsigned rank2 = atomicInc(&g_ctr, 255u);   // wraps -> replay safe
            s_glast = (rank2 == 255u);
        }
        __syncthreads();

        // ---- Last tile's block: reduce 256 tile losses ----
        if (s_glast) {
            volatile float* gp = g_tile_loss;
            float v2 = gp[t];
            #pragma unroll
            for (int off = 16; off > 0; off >>= 1)
                v2 += __shfl_xor_sync(FULL, v2, off);
            if (lane == 0) s_red[warp] = v2;
            __syncthreads();
            if (t == 0) {
                out[0] = s_red[0] + s_red[1] + s_red[2] + s_red[3]
                       + s_red[4] + s_red[5] + s_red[6] + s_red[7];
            }
        }
    }
}

// ---------------------------------------------------------------------------
// Host camera constants (reference fp32 math).
// ---------------------------------------------------------------------------
static Cam make_cam()
{
    const double PI = 3.14159265358979323846;
    double e = 0.0, a = 90.0 * PI / 180.0;
    const double CD = 2.732;
    float ex = (float)(CD * cos(e) * sin(a));
    float ey = (float)(CD * sin(e));
    float ez = (float)(-CD * cos(e) * cos(a));

    float zx = -ex, zy = -ey, zz = -ez;
    float zn = sqrtf(zx*zx + zy*zy + zz*zz);
    zx /= zn; zy /= zn; zz /= zn;
    float xx = zz, xy = 0.0f, xz = -zx;
    float xn = sqrtf(xx*xx + xy*xy + xz*xz);
    xx /= xn; xy /= xn; xz /= xn;
    float yx = zy*xz - zz*xy;
    float yy = zz*xx - zx*xz;
    float yz = zx*xy - zy*xx;
    float yn = sqrtf(yx*yx + yy*yy + yz*yz);
    yx /= yn; yy /= yn; yz /= yn;

    Cam cam;
    cam.ex = ex; cam.ey = ey; cam.ez = ez;
    cam.r00 = xx; cam.r01 = xy; cam.r02 = xz;
    cam.r10 = yx; cam.r11 = yy; cam.r12 = yz;
    cam.r20 = zx; cam.r21 = zy; cam.r22 = zz;
    cam.width = (float)tan(30.0 * PI / 180.0);
    return cam;
}

extern "C" void kernel_launch(void* const* d_in, const int* in_sizes, int n_in,
                              void* d_out, int out_size)
{
    const float* verts = (const float*)d_in[0];   // (1,512,3) f32
    const float* ref   = (const float*)d_in[1];   // (1,256,256) f32
    const int*   faces = (const int*)  d_in[2];   // (1,1024,3) i32
    float* out = (float*)d_out;

    Cam cam = make_cam();
    fused_kernel<<<1024, 256>>>(verts, faces, ref, out, cam);
}

// round 14
// speedup vs baseline: 1.0543x; 1.0543x over previous
#include <cuda_runtime.h>
#include <math.h>

#define ISZ 256
#define NV  512
#define NF  1024
#define CH  256          // faces per chunk (4 chunks per tile)

__device__ unsigned g_cov[256 * 4 * 8];   // [tile][chunk][warp-word], plain STG
__device__ float    g_tile_loss[256];
__device__ unsigned g_tctr[256];          // per-tile arrival counts (reset by consumer)
__device__ unsigned g_ctr = 0;            // tile-done counter (wrap at 255)

struct Cam {
    float ex, ey, ez;
    float r00, r01, r02, r10, r11, r12, r20, r21, r22;
    float width;
};

// ---------------------------------------------------------------------------
// Grid 1024 = 256 tiles (16x16 px) x 4 face-chunks, 256 threads.
// Prep: bbox + conservative SAT edge cull, 1 face/thread, ballot-compact.
// Fast path: full-tile-cover face -> skip the per-pixel scan.
// Chunk 3 is the static loss block for its tile: prefetches ref at start,
// spin-waits for the 3 sibling arrivals (all blocks co-resident), resets the
// counter (replay-safe), reduces. Depth test dropped (provably redundant).
// ---------------------------------------------------------------------------
__global__ __launch_bounds__(256) void fused_kernel(
    const float* __restrict__ verts,
    const int*   __restrict__ faces,
    const float* __restrict__ ref,
    float* __restrict__ out,
    Cam cam)
{
    __shared__ float  sx[NV], sy[NV];
    __shared__ float4 s_f0[CH];      // A0, B0, C0, A1
    __shared__ float2 s_f1[CH];      // B1, C1
    __shared__ float  s_red[8];
    __shared__ int    s_cnt, s_full, s_glast;

    const unsigned FULL = 0xffffffffu;
    int t     = threadIdx.x;
    int lane  = t & 31;
    int warp  = t >> 5;
    int tile  = blockIdx.x >> 2;     // 0..255
    int chunk = blockIdx.x & 3;      // 0..3
    int tx    = tile & 15;
    int ty    = tile >> 4;
    if (t == 0) { s_cnt = 0; s_full = 0; s_glast = 0; }

    int c = 16*tx + (t & 15);
    int r = 16*ty + (t >> 4);

    // ---- Prefetch face indices; loss blocks (chunk 3) also prefetch ref ----
    int f  = chunk * CH + t;
    int i0 = faces[3*f+0], i1 = faces[3*f+1], i2 = faces[3*f+2];
    float refv = 0.0f;
    if (chunk == 3) refv = ref[r * ISZ + c];

    // ---- Vertex transform: 2 verts/thread, single MUFU.RCP each ----
    #pragma unroll
    for (int v = t; v < NV; v += 256) {
        float vx = verts[3*v+0] - cam.ex;
        float vy = verts[3*v+1] - cam.ey;
        float vz = verts[3*v+2] - cam.ez;
        float cx = vx*cam.r00 + vy*cam.r01 + vz*cam.r02;
        float cy = vx*cam.r10 + vy*cam.r11 + vz*cam.r12;
        float cz = vx*cam.r20 + vy*cam.r21 + vz*cam.r22;
        float rzw = __fdividef(1.0f, cz * cam.width);
        sx[v] = cx * rzw;
        sy[v] = cy * rzw;
    }
    __syncthreads();

    // tile pixel-center bounds in NDC
    float txmin = (2.0f * (16*tx)            + 1.0f - 256.0f) * (1.0f/256.0f);
    float txmax = (2.0f * (16*tx + 15)       + 1.0f - 256.0f) * (1.0f/256.0f);
    float tymax = (2.0f * (255 - 16*ty)      + 1.0f - 256.0f) * (1.0f/256.0f);
    float tymin = (2.0f * (255 - (16*ty+15)) + 1.0f - 256.0f) * (1.0f/256.0f);

    // ---- Prep: 1 face/thread, bbox + SAT cull + full-cover detect ----
    {
        float x0 = sx[i0], x1 = sx[i1], x2 = sx[i2];
        float y0 = sy[i0], y1 = sy[i1], y2 = sy[i2];

        float denom = (y1 - y2) * (x0 - x2) + (x2 - x1) * (y0 - y2);
        bool  valid = fabsf(denom) > 1e-9f;

        float bxmin = fminf(x0, fminf(x1, x2));
        float bxmax = fmaxf(x0, fmaxf(x1, x2));
        float bymin = fminf(y0, fminf(y1, y2));
        float bymax = fmaxf(y0, fmaxf(y1, y2));

        bool acc = valid && (bxmin <= txmax) && (bxmax >= txmin) &&
                            (bymin <= tymax) && (bymax >= tymin);

        float rd = __fdividef(1.0f, denom);  // garbage if invalid; acc=false then
        float A0 = (y1 - y2) * rd, B0 = (x2 - x1) * rd;
        float A1 = (y2 - y0) * rd, B1 = (x0 - x2) * rd;
        float C0 = -(A0 * x2 + B0 * y2);
        float C1 = -(A1 * x2 + B1 * y2);
        float A2 = -(A0 + A1), B2 = -(B0 + B1), C2 = 1.0f - C0 - C1;

        // conservative max of each plane over the tile's pixel-center rect
        float e0 = A0 * (A0 > 0.0f ? txmax : txmin)
                 + B0 * (B0 > 0.0f ? tymax : tymin) + C0;
        float e1 = A1 * (A1 > 0.0f ? txmax : txmin)
                 + B1 * (B1 > 0.0f ? tymax : tymin) + C1;
        float e2 = A2 * (A2 > 0.0f ? txmax : txmin)
                 + B2 * (B2 > 0.0f ? tymax : tymin) + C2;
        acc = acc && (e0 > -1e-3f) && (e1 > -1e-3f) && (e2 > -1e-3f);

        // conservative min of each plane over the rect: full-cover test
        float m0 = A0 * (A0 > 0.0f ? txmin : txmax)
                 + B0 * (B0 > 0.0f ? tymin : tymax) + C0;
        float m1 = A1 * (A1 > 0.0f ? txmin : txmax)
                 + B1 * (B1 > 0.0f ? tymin : tymax) + C1;
        float m2 = A2 * (A2 > 0.0f ? txmin : txmax)
                 + B2 * (B2 > 0.0f ? tymin : tymax) + C2;
        if (valid && fminf(fminf(m0, m1), m2) > 1e-3f)
            s_full = 1;                      // benign race, same value

        unsigned bal = __ballot_sync(FULL, acc);
        int base = 0;
        if (lane == 0 && bal) base = atomicAdd(&s_cnt, __popc(bal));
        base = __shfl_sync(FULL, base, 0);
        if (acc) {
            int pos = base + __popc(bal & ((1u << lane) - 1u));
            s_f0[pos] = make_float4(A0, B0, C0, A1);
            s_f1[pos] = make_float2(B1, C1);
        }
    }
    __syncthreads();
    int n = s_cnt;

    bool cov;
    if (s_full) {
        cov = true;                          // some face covers the whole tile
    } else {
        // ---- Per-pixel running-max plane scan ----
        float xs = (2.0f * c + 1.0f - 256.0f) * (1.0f/256.0f);
        float ys = (2.0f * (255 - r) + 1.0f - 256.0f) * (1.0f/256.0f);

        float best = -1e30f;
        #pragma unroll 8
        for (int j = 0; j < n; j++) {
            float4 f0 = s_f0[j];
            float2 f1 = s_f1[j];
            float w0 = f0.x * xs + f0.y * ys + f0.z;
            float w1 = f0.w * xs + f1.x * ys + f1.y;
            float w2 = 1.0f - w0 - w1;
            best = fmaxf(best, fminf(fminf(w0, w1), w2));
            if ((j & 7) == 7 && __all_sync(FULL, best > 0.0f)) break;
        }
        cov = best > 0.0f;
    }

    // ---- Write coverage word (unconditional STG -> replay-deterministic) ----
    unsigned bits = __ballot_sync(FULL, cov);
    if (lane == 0)
        g_cov[(tile * 4 + chunk) * 8 + warp] = bits;
    __syncthreads();

    if (chunk != 3) {
        // ---- Producer chunks: publish arrival and exit ----
        if (t == 0) {
            __threadfence();
            atomicAdd(&g_tctr[tile], 1u);
        }
        return;
    }

    // ---- Chunk 3: wait for siblings (all blocks co-resident -> safe) ----
    if (t == 0) {
        __threadfence();
        unsigned v;
        do { v = atomicAdd(&g_tctr[tile], 0u); } while (v < 3u);
        g_tctr[tile] = 0u;                   // reset for next graph replay
        __threadfence();
    }
    __syncthreads();

    {
        unsigned w = bits;                   // own chunk's word is in-register? no: per-warp
        const unsigned* vc = g_cov + tile * 32;
        unsigned ww = vc[warp] | vc[8 + warp] | vc[16 + warp] | vc[24 + warp];
        float covf = (float)((ww >> lane) & 1u);
        float d = covf - refv;
        float v = d * d;
        #pragma unroll
        for (int off = 16; off > 0; off >>= 1)
            v += __shfl_xor_sync(FULL, v, off);
        if (lane == 0) s_red[warp] = v;
        __syncthreads();
        if (t == 0) {
            float acc = s_red[0] + s_red[1] + s_red[2] + s_red[3]
                      + s_red[4] + s_red[5] + s_red[6] + s_red[7];
            g_tile_loss[tile] = acc;
            __threadfence();
            unsigned rank2 = atomicInc(&g_ctr, 255u);   // wraps -> replay safe
            s_glast = (rank2 == 255u);
        }
        __syncthreads();

        // ---- Last tile's loss block: reduce 256 tile losses ----
        if (s_glast) {
            volatile float* gp = g_tile_loss;
            float v2 = gp[t];
            #pragma unroll
            for (int off = 16; off > 0; off >>= 1)
                v2 += __shfl_xor_sync(FULL, v2, off);
            if (lane == 0) s_red[warp] = v2;
            __syncthreads();
            if (t == 0) {
                out[0] = s_red[0] + s_red[1] + s_red[2] + s_red[3]
                       + s_red[4] + s_red[5] + s_red[6] + s_red[7];
            }
        }
    }
}

// ---------------------------------------------------------------------------
// Host camera constants (reference fp32 math).
// ---------------------------------------------------------------------------
static Cam make_cam()
{
    const double PI = 3.14159265358979323846;
    double e = 0.0, a = 90.0 * PI / 180.0;
    const double CD = 2.732;
    float ex = (float)(CD * cos(e) * sin(a));
    float ey = (float)(CD * sin(e));
    float ez = (float)(-CD * cos(e) * cos(a));

    float zx = -ex, zy = -ey, zz = -ez;
    float zn = sqrtf(zx*zx + zy*zy + zz*zz);
    zx /= zn; zy /= zn; zz /= zn;
    float xx = zz, xy = 0.0f, xz = -zx;
    float xn = sqrtf(xx*xx + xy*xy + xz*xz);
    xx /= xn; xy /= xn; xz /= xn;
    float yx = zy*xz - zz*xy;
    float yy = zz*xx - zx*xz;
    float yz = zx*xy - zy*xx;
    float yn = sqrtf(yx*yx + yy*yy + yz*yz);
    yx /= yn; yy /= yn; yz /= yn;

    Cam cam;
    cam.ex = ex; cam.ey = ey; cam.ez = ez;
    cam.r00 = xx; cam.r01 = xy; cam.r02 = xz;
    cam.r10 = yx; cam.r11 = yy; cam.r12 = yz;
    cam.r20 = zx; cam.r21 = zy; cam.r22 = zz;
    cam.width = (float)tan(30.0 * PI / 180.0);
    return cam;
}

extern "C" void kernel_launch(void* const* d_in, const int* in_sizes, int n_in,
                              void* d_out, int out_size)
{
    const float* verts = (const float*)d_in[0];   // (1,512,3) f32
    const float* ref   = (const float*)d_in[1];   // (1,256,256) f32
    const int*   faces = (const int*)  d_in[2];   // (1,1024,3) i32
    float* out = (float*)d_out;

    Cam cam = make_cam();
    fused_kernel<<<1024, 256>>>(verts, faces, ref, out, cam);
}

// round 15
// speedup vs baseline: 1.2143x; 1.1518x over previous
#include <cuda_runtime.h>
#include <math.h>

#define ISZ 256
#define NV  512
#define NF  1024
#define CH  256          // faces per chunk (4 chunks per tile)

__device__ unsigned g_cov[256 * 4 * 8];   // [tile][chunk][warp-word], plain STG
__device__ float    g_tile_loss[256];
__device__ unsigned g_tctr[256];          // per-tile arrival counters (wrap at 3)
__device__ unsigned g_ctr = 0;            // tile-done counter (wrap at 255)

struct Cam {
    float ex, ey, ez;
    float r00, r01, r02, r10, r11, r12, r20, r21, r22;
    float width;
};

// ---------------------------------------------------------------------------
// Grid 1024 = 256 tiles (16x16 px) x 4 face-chunks, 256 threads.
// Prep: bbox + conservative SAT edge cull (center+extent form), 1 face/thread,
// ballot-compact. Fast path: full-tile-cover face -> skip per-pixel scan.
// Coverage merged via plain per-(tile,chunk) STG words (overwritten every
// replay -> deterministic), ordered by fence + wrap counters.
// Depth test dropped (provably always passes for interior pixels here).
// ---------------------------------------------------------------------------
__global__ __launch_bounds__(256) void fused_kernel(
    const float* __restrict__ verts,
    const int*   __restrict__ faces,
    const float* __restrict__ ref,
    float* __restrict__ out,
    Cam cam)
{
    __shared__ float  sx[NV], sy[NV];
    __shared__ float4 s_f0[CH];      // A0, B0, C0, A1
    __shared__ float2 s_f1[CH];      // B1, C1
    __shared__ float  s_red[8];
    __shared__ int    s_cnt, s_full, s_tlast, s_glast;

    const unsigned FULL = 0xffffffffu;
    int t     = threadIdx.x;
    int lane  = t & 31;
    int warp  = t >> 5;
    int tile  = blockIdx.x >> 2;     // 0..255
    int chunk = blockIdx.x & 3;      // 0..3
    int tx    = tile & 15;
    int ty    = tile >> 4;
    if (t == 0) { s_cnt = 0; s_full = 0; s_tlast = 0; s_glast = 0; }

    // ---- Prefetch own face indices (overlaps the vertex-transform chain) ----
    int f  = chunk * CH + t;
    int i0 = faces[3*f+0], i1 = faces[3*f+1], i2 = faces[3*f+2];

    // ---- Vertex transform: 2 verts/thread (approx rcp; ~2.4e-7 rel) ----
    #pragma unroll
    for (int v = t; v < NV; v += 256) {
        float vx = verts[3*v+0] - cam.ex;
        float vy = verts[3*v+1] - cam.ey;
        float vz = verts[3*v+2] - cam.ez;
        float cx = vx*cam.r00 + vy*cam.r01 + vz*cam.r02;
        float cy = vx*cam.r10 + vy*cam.r11 + vz*cam.r12;
        float cz = vx*cam.r20 + vy*cam.r21 + vz*cam.r22;
        float zw = cz * cam.width;
        sx[v] = __fdividef(cx, zw);
        sy[v] = __fdividef(cy, zw);
    }
    __syncthreads();

    // tile pixel-center bounds in NDC
    float txmin = (2.0f * (16*tx)            + 1.0f - 256.0f) * (1.0f/256.0f);
    float txmax = (2.0f * (16*tx + 15)       + 1.0f - 256.0f) * (1.0f/256.0f);
    float tymax = (2.0f * (255 - 16*ty)      + 1.0f - 256.0f) * (1.0f/256.0f);
    float tymin = (2.0f * (255 - (16*ty+15)) + 1.0f - 256.0f) * (1.0f/256.0f);
    // center + half-extents
    float xc = 0.5f * (txmin + txmax), hx = 0.5f * (txmax - txmin);
    float yc = 0.5f * (tymin + tymax), hy = 0.5f * (tymax - tymin);

    // ---- Prep: 1 face/thread, bbox + SAT cull + full-cover detect ----
    {
        float x0 = sx[i0], x1 = sx[i1], x2 = sx[i2];
        float y0 = sy[i0], y1 = sy[i1], y2 = sy[i2];

        float denom = (y1 - y2) * (x0 - x2) + (x2 - x1) * (y0 - y2);
        bool  valid = fabsf(denom) > 1e-9f;

        float bxmin = fminf(x0, fminf(x1, x2));
        float bxmax = fmaxf(x0, fmaxf(x1, x2));
        float bymin = fminf(y0, fminf(y1, y2));
        float bymax = fmaxf(y0, fmaxf(y1, y2));

        bool acc = valid && (bxmin <= txmax) && (bxmax >= txmin) &&
                            (bymin <= tymax) && (bymax >= tymin);

        float rd = __fdividef(1.0f, denom);  // garbage if invalid; acc=false then
        float A0 = (y1 - y2) * rd, B0 = (x2 - x1) * rd;
        float A1 = (y2 - y0) * rd, B1 = (x0 - x2) * rd;
        float C0 = -(A0 * x2 + B0 * y2);
        float C1 = -(A1 * x2 + B1 * y2);
        float A2 = -(A0 + A1), B2 = -(B0 + B1), C2 = 1.0f - C0 - C1;

        // center value + conservative half-range of each plane over the rect
        float T0 = A0 * xc + B0 * yc + C0;
        float T1 = A1 * xc + B1 * yc + C1;
        float T2 = A2 * xc + B2 * yc + C2;
        float U0 = fabsf(A0) * hx + fabsf(B0) * hy;
        float U1 = fabsf(A1) * hx + fabsf(B1) * hy;
        float U2 = fabsf(A2) * hx + fabsf(B2) * hy;

        // max over rect > -1e-3 for all planes, else cull
        acc = acc && (T0 + U0 > -1e-3f) && (T1 + U1 > -1e-3f) &&
                     (T2 + U2 > -1e-3f);

        // min over rect > 1e-3 for all planes -> full tile covered
        if (valid && fminf(fminf(T0 - U0, T1 - U1), T2 - U2) > 1e-3f)
            s_full = 1;                      // benign race, same value

        unsigned bal = __ballot_sync(FULL, acc);
        int base = 0;
        if (lane == 0 && bal) base = atomicAdd(&s_cnt, __popc(bal));
        base = __shfl_sync(FULL, base, 0);
        if (acc) {
            int pos = base + __popc(bal & ((1u << lane) - 1u));
            s_f0[pos] = make_float4(A0, B0, C0, A1);
            s_f1[pos] = make_float2(B1, C1);
        }
    }
    __syncthreads();
    int n = s_cnt;

    int c = 16*tx + (t & 15);
    int r = 16*ty + (t >> 4);

    bool cov;
    if (s_full) {
        cov = true;                          // some face covers the whole tile
    } else {
        // ---- Per-pixel running-max plane scan ----
        float xs = (2.0f * c + 1.0f - 256.0f) * (1.0f/256.0f);
        float ys = (2.0f * (255 - r) + 1.0f - 256.0f) * (1.0f/256.0f);

        float best = -1e30f;
        #pragma unroll 8
        for (int j = 0; j < n; j++) {
            float4 f0 = s_f0[j];
            float2 f1 = s_f1[j];
            float w0 = f0.x * xs + f0.y * ys + f0.z;
            float w1 = f0.w * xs + f1.x * ys + f1.y;
            float w2 = 1.0f - w0 - w1;
            best = fmaxf(best, fminf(fminf(w0, w1), w2));
            if ((j & 7) == 7 && __all_sync(FULL, best > 0.0f)) break;
        }
        cov = best > 0.0f;
    }

    // ---- Write coverage word (unconditional STG -> replay-deterministic) ----
    unsigned bits = __ballot_sync(FULL, cov);
    if (lane == 0)
        g_cov[(tile * 4 + chunk) * 8 + warp] = bits;
    __syncthreads();

    // ---- Per-tile arrival; 4th block computes the tile's loss ----
    if (t == 0) {
        __threadfence();
        unsigned rank = atomicInc(&g_tctr[tile], 3u);   // wraps -> replay safe
        s_tlast = (rank == 3u);
    }
    __syncthreads();

    if (s_tlast) {
        volatile unsigned* vc = g_cov + tile * 32;
        unsigned w = vc[warp] | vc[8 + warp] | vc[16 + warp] | vc[24 + warp];
        float covf = (float)((w >> lane) & 1u);
        float d = covf - ref[r * ISZ + c];
        float v = d * d;
        #pragma unroll
        for (int off = 16; off > 0; off >>= 1)
            v += __shfl_xor_sync(FULL, v, off);
        if (lane == 0) s_red[warp] = v;
        __syncthreads();
        if (t == 0) {
            float acc = s_red[0] + s_red[1] + s_red[2] + s_red[3]
                      + s_red[4] + s_red[5] + s_red[6] + s_red[7];
            g_tile_loss[tile] = acc;
            __threadfence();
            unsigned rank2 = atomicInc(&g_ctr, 255u);   // wraps -> replay safe
            s_glast = (rank2 == 255u);
        }
        __syncthreads();

        // ---- Last tile's block: reduce 256 tile losses ----
        if (s_glast) {
            volatile float* gp = g_tile_loss;
            float v2 = gp[t];
            #pragma unroll
            for (int off = 16; off > 0; off >>= 1)
                v2 += __shfl_xor_sync(FULL, v2, off);
            if (lane == 0) s_red[warp] = v2;
            __syncthreads();
            if (t == 0) {
                out[0] = s_red[0] + s_red[1] + s_red[2] + s_red[3]
                       + s_red[4] + s_red[5] + s_red[6] + s_red[7];
            }
        }
    }
}

// ---------------------------------------------------------------------------
// Host camera constants (reference fp32 math).
// ---------------------------------------------------------------------------
static Cam make_cam()
{
    const double PI = 3.14159265358979323846;
    double e = 0.0, a = 90.0 * PI / 180.0;
    const double CD = 2.732;
    float ex = (float)(CD * cos(e) * sin(a));
    float ey = (float)(CD * sin(e));
    float ez = (float)(-CD * cos(e) * cos(a));

    float zx = -ex, zy = -ey, zz = -ez;
    float zn = sqrtf(zx*zx + zy*zy + zz*zz);
    zx /= zn; zy /= zn; zz /= zn;
    float xx = zz, xy = 0.0f, xz = -zx;
    float xn = sqrtf(xx*xx + xy*xy + xz*xz);
    xx /= xn; xy /= xn; xz /= xn;
    float yx = zy*xz - zz*xy;
    float yy = zz*xx - zx*xz;
    float yz = zx*xy - zy*xx;
    float yn = sqrtf(yx*yx + yy*yy + yz*yz);
    yx /= yn; yy /= yn; yz /= yn;

    Cam cam;
    cam.ex = ex; cam.ey = ey; cam.ez = ez;
    cam.r00 = xx; cam.r01 = xy; cam.r02 = xz;
    cam.r10 = yx; cam.r11 = yy; cam.r12 = yz;
    cam.r20 = zx; cam.r21 = zy; cam.r22 = zz;
    cam.width = (float)tan(30.0 * PI / 180.0);
    return cam;
}

extern "C" void kernel_launch(void* const* d_in, const int* in_sizes, int n_in,
                              void* d_out, int out_size)
{
    const float* verts = (const float*)d_in[0];   // (1,512,3) f32
    const float* ref   = (const float*)d_in[1];   // (1,256,256) f32
    const int*   faces = (const int*)  d_in[2];   // (1,1024,3) i32
    float* out = (float*)d_out;

    Cam cam = make_cam();
    fused_kernel<<<1024, 256>>>(verts, faces, ref, out, cam);
}